// round 8
// baseline (speedup 1.0000x reference)
#include <cuda_runtime.h>
#include <cuda_bf16.h>
#include <cstdint>

#define N_NODES 100000
#define N_EDGES 3200000
#define HID 128
#define N_GRAPHS 512

// ---------------- scratch (device globals; no allocation allowed) ----------
__device__ uint32_t g_Th[(size_t)N_NODES * 64];  // T as packed bf16x2 (128 cols)
__device__ float g_A[(size_t)N_NODES * HID];     // aggregated output (fp32)
__device__ float g_deg[N_NODES];
__device__ float g_dinv[N_NODES];
__device__ float g_pool[N_GRAPHS * HID];
__device__ float g_cnt[N_GRAPHS];
// CSR (by destination)
__device__ int   g_row_ptr[N_NODES + 1];
__device__ int   g_row_fill[N_NODES];
__device__ int   g_col_src[N_EDGES];
__device__ float g_col_w[N_EDGES];
__device__ int   g_hist[N_NODES];

#define SCAN_BLK 391            // ceil(100000/256)
__device__ int   g_bsum[512];   // block sums (padded)

// tf32 B-fragments for all 4 layers:
// layout [layer][s2(8)][t(16)][lane(32)] -> float4 = (b0_even, b1_even, b0_odd, b1_odd)
__device__ float4 g_Wfrag[4 * 8 * 16 * 32];

__device__ __forceinline__ uint32_t cvt_tf32(float f) {
    uint32_t u;
    asm("cvt.rna.tf32.f32 %0, %1;" : "=r"(u) : "f"(f));
    return u;
}

// ---------------- degree / norm ----------------
__global__ void k_init_deg() {
    int i = blockIdx.x * blockDim.x + threadIdx.x;
    if (i < N_NODES) { g_deg[i] = 1.0f; g_hist[i] = 0; }   // self-loop weight
}

__global__ void k_accum_deg(const int* __restrict__ ei, const float* __restrict__ ew) {
    int e = blockIdx.x * blockDim.x + threadIdx.x;
    if (e >= N_EDGES) return;
    int dst = ei[N_EDGES + e];
    atomicAdd(&g_deg[dst], ew[e]);
    atomicAdd(&g_hist[dst], 1);
}

__global__ void k_dinv() {
    int i = blockIdx.x * blockDim.x + threadIdx.x;
    if (i < N_NODES) g_dinv[i] = rsqrtf(g_deg[i]);   // deg >= 1 always
}

// ---------------- 3-phase parallel exclusive scan over g_hist --------------
__global__ void k_scan1() {
    __shared__ int sh[256];
    int i = blockIdx.x * 256 + threadIdx.x;
    int v = (i < N_NODES) ? g_hist[i] : 0;
    sh[threadIdx.x] = v;
    __syncthreads();
    #pragma unroll
    for (int o = 128; o > 0; o >>= 1) {
        if (threadIdx.x < o) sh[threadIdx.x] += sh[threadIdx.x + o];
        __syncthreads();
    }
    if (threadIdx.x == 0) g_bsum[blockIdx.x] = sh[0];
}

__global__ void k_scan2() {
    __shared__ int sh[512];
    int t = threadIdx.x;
    sh[t] = (t < SCAN_BLK) ? g_bsum[t] : 0;
    __syncthreads();
    #pragma unroll
    for (int o = 1; o < 512; o <<= 1) {
        int v = (t >= o) ? sh[t - o] : 0;
        __syncthreads();
        sh[t] += v;
        __syncthreads();
    }
    if (t < SCAN_BLK) g_bsum[t] = (t == 0) ? 0 : sh[t - 1];   // exclusive
}

__global__ void k_scan3() {
    __shared__ int sh[256];
    int t = threadIdx.x;
    int i = blockIdx.x * 256 + t;
    int v = (i < N_NODES) ? g_hist[i] : 0;
    sh[t] = v;
    __syncthreads();
    #pragma unroll
    for (int o = 1; o < 256; o <<= 1) {
        int u = (t >= o) ? sh[t - o] : 0;
        __syncthreads();
        sh[t] += u;
        __syncthreads();
    }
    if (i < N_NODES) {
        int off = g_bsum[blockIdx.x] + sh[t] - v;   // exclusive
        g_row_ptr[i] = off;
        g_row_fill[i] = off;
    }
    if (i == 0) g_row_ptr[N_NODES] = N_EDGES;
}

// ---------------- fill CSR: col_src + fused norm weight --------------------
__global__ void k_fill(const int* __restrict__ ei, const float* __restrict__ ew) {
    int e = blockIdx.x * blockDim.x + threadIdx.x;
    if (e >= N_EDGES) return;
    int src = ei[e], dst = ei[N_EDGES + e];
    int pos = atomicAdd(&g_row_fill[dst], 1);
    g_col_src[pos] = src;
    g_col_w[pos] = g_dinv[src] * ew[e] * g_dinv[dst];
}

// ---------------- precompute W tf32 fragments (all 4 layers) ---------------
__global__ void k_wfrag(const float* __restrict__ W0, const float* __restrict__ W1,
                        const float* __restrict__ W2, const float* __restrict__ W3) {
    int idx = blockIdx.x * 256 + threadIdx.x;     // 4*8*16*32 = 16384
    if (idx >= 4 * 8 * 16 * 32) return;
    int layer = idx >> 12;
    int rem = idx & 4095;
    int s2 = rem >> 9;           // k-step pair (0..7)
    int t  = (rem >> 5) & 15;    // n-tile (0..15)
    int lane = rem & 31;
    int tg = lane & 3, gid = lane >> 2;
    const float* W = (layer == 0) ? W0 : (layer == 1) ? W1 : (layer == 2) ? W2 : W3;
    int n = t * 8 + gid;
    int k0 = s2 * 16;
    float4 v;
    v.x = __uint_as_float(cvt_tf32(W[(k0 + tg) * HID + n]));
    v.y = __uint_as_float(cvt_tf32(W[(k0 + tg + 4) * HID + n]));
    v.z = __uint_as_float(cvt_tf32(W[(k0 + 8 + tg) * HID + n]));
    v.w = __uint_as_float(cvt_tf32(W[(k0 + 12 + tg) * HID + n]));
    g_Wfrag[idx] = v;
}

// ---------------- GEMM via mma.sync tf32: Th = bf16(act(X) @ W) ------------
#define GTILE 128
#define XS_STRIDE 132
#define GEMM_SMEM (GTILE * XS_STRIDE * 4)

__device__ __forceinline__ void mma_tf32(float* d, uint32_t a0, uint32_t a1,
                                         uint32_t a2, uint32_t a3,
                                         float bx, float by) {
    asm volatile(
        "mma.sync.aligned.m16n8k8.row.col.f32.tf32.tf32.f32 "
        "{%0,%1,%2,%3}, {%4,%5,%6,%7}, {%8,%9}, {%0,%1,%2,%3};"
        : "+f"(d[0]), "+f"(d[1]), "+f"(d[2]), "+f"(d[3])
        : "r"(a0), "r"(a1), "r"(a2), "r"(a3),
          "r"(__float_as_uint(bx)), "r"(__float_as_uint(by)));
}

__device__ __forceinline__ uint32_t pack_bf16x2(float a, float b) {
    __nv_bfloat162 h = __float22bfloat162_rn(make_float2(a, b));
    return *(uint32_t*)&h;
}

__global__ void __launch_bounds__(256) k_gemm_mma(const float* __restrict__ X,
                                                  int layer, int relu_in) {
    extern __shared__ uint32_t Xs[];   // [128][132] tf32 bits
    int tid = threadIdx.x;
    int wid = tid >> 5;
    int lane = tid & 31;
    int row0 = blockIdx.x * GTILE;

    // stage X tile (relu + tf32 convert)
    #pragma unroll
    for (int it = 0; it < 16; it++) {
        int i = tid + it * 256;            // row = i>>5, kg = i&31
        int row = i >> 5;
        int kg = i & 31;
        int grow = row0 + row;
        float4 v = make_float4(0.f, 0.f, 0.f, 0.f);
        if (grow < N_NODES) {
            v = *(const float4*)(X + (size_t)grow * HID + kg * 4);
            if (relu_in) {
                v.x = fmaxf(v.x, 0.f); v.y = fmaxf(v.y, 0.f);
                v.z = fmaxf(v.z, 0.f); v.w = fmaxf(v.w, 0.f);
            }
        }
        uint32_t* dst = Xs + row * XS_STRIDE + kg * 4;
        dst[0] = cvt_tf32(v.x); dst[1] = cvt_tf32(v.y);
        dst[2] = cvt_tf32(v.z); dst[3] = cvt_tf32(v.w);
    }
    __syncthreads();

    int tg = lane & 3, gid = lane >> 2;
    float acc[16][4];
    #pragma unroll
    for (int t = 0; t < 16; t++)
        #pragma unroll
        for (int j = 0; j < 4; j++) acc[t][j] = 0.f;

    const uint32_t* arow_lo = Xs + (wid * 16 + gid) * XS_STRIDE;
    const uint32_t* arow_hi = arow_lo + 8 * XS_STRIDE;
    const float4* frag = g_Wfrag + (size_t)layer * 4096 + lane;

    #pragma unroll
    for (int s2 = 0; s2 < 8; s2++) {
        int k0 = s2 * 16;
        uint32_t ae0 = arow_lo[k0 + tg];
        uint32_t ae1 = arow_hi[k0 + tg];
        uint32_t ae2 = arow_lo[k0 + tg + 4];
        uint32_t ae3 = arow_hi[k0 + tg + 4];
        uint32_t ao0 = arow_lo[k0 + 8 + tg];
        uint32_t ao1 = arow_hi[k0 + 8 + tg];
        uint32_t ao2 = arow_lo[k0 + 12 + tg];
        uint32_t ao3 = arow_hi[k0 + 12 + tg];
        const float4* f = frag + s2 * 512;   // [t][lane] stride 32
        #pragma unroll
        for (int t = 0; t < 16; t++) {
            float4 b = f[t * 32];
            mma_tf32(acc[t], ae0, ae1, ae2, ae3, b.x, b.y);
            mma_tf32(acc[t], ao0, ao1, ao2, ao3, b.z, b.w);
        }
    }

    // epilogue: pack to bf16x2; col = t*8 + tg*2 -> word idx t*4 + tg
    int row_lo = row0 + wid * 16 + gid;
    int row_hi = row_lo + 8;
    #pragma unroll
    for (int t = 0; t < 16; t++) {
        int widx = t * 4 + tg;
        if (row_lo < N_NODES)
            g_Th[(size_t)row_lo * 64 + widx] = pack_bf16x2(acc[t][0], acc[t][1]);
        if (row_hi < N_NODES)
            g_Th[(size_t)row_hi * 64 + widx] = pack_bf16x2(acc[t][2], acc[t][3]);
    }
}

// ---------------- aggregate: A[d] = b + Th[d]*dinv^2 + sum_e w_e*Th[src_e] ----
// warp per destination; lane owns 4 cols = 2 bf16x2 words (uint2 gather)
__device__ __forceinline__ void bf2_fma(float4& acc, uint2 p, float w) {
    float2 lo = __bfloat1622float2(*(__nv_bfloat162*)&p.x);
    float2 hi = __bfloat1622float2(*(__nv_bfloat162*)&p.y);
    acc.x += lo.x * w; acc.y += lo.y * w; acc.z += hi.x * w; acc.w += hi.y * w;
}

__global__ void k_aggregate(const float* __restrict__ b) {
    int node = (blockIdx.x * blockDim.x + threadIdx.x) >> 5;
    int lane = threadIdx.x & 31;
    if (node >= N_NODES) return;

    int beg = __ldg(&g_row_ptr[node]);
    int end = __ldg(&g_row_ptr[node + 1]);
    float di = __ldg(&g_dinv[node]);
    float sw = di * di;   // self-loop weight

    float4 acc = ((const float4*)b)[lane];
    uint2 ts = *(const uint2*)(g_Th + (size_t)node * 64 + lane * 2);
    bf2_fma(acc, ts, sw);

    int e = beg;
    for (; e + 4 <= end; e += 4) {
        int   s0 = __ldg(&g_col_src[e + 0]);
        int   s1 = __ldg(&g_col_src[e + 1]);
        int   s2 = __ldg(&g_col_src[e + 2]);
        int   s3 = __ldg(&g_col_src[e + 3]);
        float w0 = __ldg(&g_col_w[e + 0]);
        float w1 = __ldg(&g_col_w[e + 1]);
        float w2 = __ldg(&g_col_w[e + 2]);
        float w3 = __ldg(&g_col_w[e + 3]);
        uint2 v0 = *(const uint2*)(g_Th + (size_t)s0 * 64 + lane * 2);
        uint2 v1 = *(const uint2*)(g_Th + (size_t)s1 * 64 + lane * 2);
        uint2 v2 = *(const uint2*)(g_Th + (size_t)s2 * 64 + lane * 2);
        uint2 v3 = *(const uint2*)(g_Th + (size_t)s3 * 64 + lane * 2);
        bf2_fma(acc, v0, w0);
        bf2_fma(acc, v1, w1);
        bf2_fma(acc, v2, w2);
        bf2_fma(acc, v3, w3);
    }
    for (; e < end; e++) {
        int   s = __ldg(&g_col_src[e]);
        float w = __ldg(&g_col_w[e]);
        uint2 v = *(const uint2*)(g_Th + (size_t)s * 64 + lane * 2);
        bf2_fma(acc, v, w);
    }
    ((float4*)(g_A + (size_t)node * HID))[lane] = acc;
}

// ---------------- pooling ----------------
__global__ void k_zero_pool() {
    int i = blockIdx.x * blockDim.x + threadIdx.x;
    if (i < N_GRAPHS * HID) g_pool[i] = 0.f;
    if (i < N_GRAPHS) g_cnt[i] = 0.f;
}

__global__ void k_pool(const int* __restrict__ batch) {
    int w = (blockIdx.x * blockDim.x + threadIdx.x) >> 5;
    int lane = threadIdx.x & 31;
    if (w >= N_NODES) return;
    int g = __ldg(&batch[w]);
    float4 v = ((const float4*)(g_A + (size_t)w * HID))[lane];
    v.x = fmaxf(v.x, 0.f); v.y = fmaxf(v.y, 0.f);
    v.z = fmaxf(v.z, 0.f); v.w = fmaxf(v.w, 0.f);
    float* d = g_pool + g * HID + lane * 4;
    asm volatile("red.global.add.v4.f32 [%0], {%1,%2,%3,%4};"
                 :: "l"(d), "f"(v.x), "f"(v.y), "f"(v.z), "f"(v.w) : "memory");
    if (lane == 0) atomicAdd(&g_cnt[g], 1.0f);
}

// ---------------- head ----------------
__global__ void k_final(const float* __restrict__ Wc, const float* __restrict__ bc,
                        float* __restrict__ out) {
    int g = blockIdx.x;
    int c = threadIdx.x;     // 128
    float cn = fmaxf(g_cnt[g], 1.0f);
    float v = g_pool[g * HID + c] / cn * Wc[c];
    #pragma unroll
    for (int o = 16; o > 0; o >>= 1) v += __shfl_down_sync(0xffffffffu, v, o);
    __shared__ float ss[4];
    if ((c & 31) == 0) ss[c >> 5] = v;
    __syncthreads();
    if (c == 0) {
        float s = ss[0] + ss[1] + ss[2] + ss[3] + bc[0];
        out[g] = 1.0f / (1.0f + expf(-s));
    }
}

// ---------------- launch ----------------
extern "C" void kernel_launch(void* const* d_in, const int* in_sizes, int n_in,
                              void* d_out, int out_size) {
    const float* x   = (const float*)d_in[0];
    const int*   ei  = (const int*)d_in[1];
    const float* ew  = (const float*)d_in[2];
    const int*   bat = (const int*)d_in[3];
    const float* W[4]  = { (const float*)d_in[4], (const float*)d_in[6],
                           (const float*)d_in[8], (const float*)d_in[10] };
    const float* B[4]  = { (const float*)d_in[5], (const float*)d_in[7],
                           (const float*)d_in[9], (const float*)d_in[11] };
    const float* Wc  = (const float*)d_in[12];
    const float* bc  = (const float*)d_in[13];
    float* out = (float*)d_out;

    cudaFuncSetAttribute(k_gemm_mma, cudaFuncAttributeMaxDynamicSharedMemorySize,
                         GEMM_SMEM);

    float* A_ptr; cudaGetSymbolAddress((void**)&A_ptr, g_A);

    // ---- preprocessing: degrees + CSR build + W fragments ----
    k_init_deg<<<(N_NODES + 255) / 256, 256>>>();
    k_accum_deg<<<(N_EDGES + 255) / 256, 256>>>(ei, ew);
    k_dinv<<<(N_NODES + 255) / 256, 256>>>();
    k_scan1<<<SCAN_BLK, 256>>>();
    k_scan2<<<1, 512>>>();
    k_scan3<<<SCAN_BLK, 256>>>();
    k_fill<<<(N_EDGES + 255) / 256, 256>>>(ei, ew);
    k_wfrag<<<64, 256>>>(W[0], W[1], W[2], W[3]);

    const int gemm_grid = (N_NODES + GTILE - 1) / GTILE;     // 782
    const int aggr_grid = (N_NODES * 32 + 255) / 256;        // warp per node

    // ---- 4 GCN layers ----
    for (int l = 0; l < 4; l++) {
        const float* in = (l == 0) ? x : A_ptr;
        int relu_in = (l == 0) ? 0 : 1;
        k_gemm_mma<<<gemm_grid, 256, GEMM_SMEM>>>(in, l, relu_in);
        k_aggregate<<<aggr_grid, 256>>>(B[l]);
    }

    // ---- pooling + head ----
    k_zero_pool<<<(N_GRAPHS * HID + 255) / 256, 256>>>();
    k_pool<<<(N_NODES * 32 + 255) / 256, 256>>>(bat);
    k_final<<<N_GRAPHS, HID>>>(Wc, bc, out);
}

// round 9
// speedup vs baseline: 1.2712x; 1.2712x over previous
#include <cuda_runtime.h>
#include <cuda_bf16.h>
#include <cstdint>

#define N_NODES 100000
#define N_EDGES 3200000
#define HID 128
#define N_GRAPHS 512

// ---------------- scratch (device globals; no allocation allowed) ----------
__device__ float g_T[(size_t)N_NODES * HID];     // tmp = act(input) @ W (fp32)
__device__ float g_A[(size_t)N_NODES * HID];     // aggregated output
__device__ float g_deg[N_NODES];
__device__ float g_dinv[N_NODES];
__device__ float g_pool[N_GRAPHS * HID];
__device__ float g_cnt[N_GRAPHS];
// CSR (by destination) — interleaved (src, weight_bits)
__device__ int   g_row_ptr[N_NODES + 1];
__device__ int   g_row_fill[N_NODES];
__device__ int2  g_col[N_EDGES];
__device__ int   g_hist[N_NODES];

#define SCAN_BLK 391            // ceil(100000/256)
__device__ int   g_bsum[512];   // block sums (padded)

// tf32 B-fragments for all 4 layers:
// layout [layer][s2(8)][t(16)][lane(32)] -> float4 = (b0_even, b1_even, b0_odd, b1_odd)
__device__ float4 g_Wfrag[4 * 8 * 16 * 32];

__device__ __forceinline__ uint32_t cvt_tf32(float f) {
    uint32_t u;
    asm("cvt.rna.tf32.f32 %0, %1;" : "=r"(u) : "f"(f));
    return u;
}

// ---------------- degree / norm ----------------
__global__ void k_init_deg() {
    int i = blockIdx.x * blockDim.x + threadIdx.x;
    if (i < N_NODES) { g_deg[i] = 1.0f; g_hist[i] = 0; }   // self-loop weight
}

__global__ void k_accum_deg(const int* __restrict__ ei, const float* __restrict__ ew) {
    int e = blockIdx.x * blockDim.x + threadIdx.x;
    if (e >= N_EDGES) return;
    int dst = ei[N_EDGES + e];
    atomicAdd(&g_deg[dst], ew[e]);
    atomicAdd(&g_hist[dst], 1);
}

__global__ void k_dinv() {
    int i = blockIdx.x * blockDim.x + threadIdx.x;
    if (i < N_NODES) g_dinv[i] = rsqrtf(g_deg[i]);   // deg >= 1 always
}

// ---------------- 3-phase parallel exclusive scan over g_hist --------------
__global__ void k_scan1() {
    __shared__ int sh[256];
    int i = blockIdx.x * 256 + threadIdx.x;
    int v = (i < N_NODES) ? g_hist[i] : 0;
    sh[threadIdx.x] = v;
    __syncthreads();
    #pragma unroll
    for (int o = 128; o > 0; o >>= 1) {
        if (threadIdx.x < o) sh[threadIdx.x] += sh[threadIdx.x + o];
        __syncthreads();
    }
    if (threadIdx.x == 0) g_bsum[blockIdx.x] = sh[0];
}

__global__ void k_scan2() {
    __shared__ int sh[512];
    int t = threadIdx.x;
    sh[t] = (t < SCAN_BLK) ? g_bsum[t] : 0;
    __syncthreads();
    #pragma unroll
    for (int o = 1; o < 512; o <<= 1) {
        int v = (t >= o) ? sh[t - o] : 0;
        __syncthreads();
        sh[t] += v;
        __syncthreads();
    }
    if (t < SCAN_BLK) g_bsum[t] = (t == 0) ? 0 : sh[t - 1];   // exclusive
}

__global__ void k_scan3() {
    __shared__ int sh[256];
    int t = threadIdx.x;
    int i = blockIdx.x * 256 + t;
    int v = (i < N_NODES) ? g_hist[i] : 0;
    sh[t] = v;
    __syncthreads();
    #pragma unroll
    for (int o = 1; o < 256; o <<= 1) {
        int u = (t >= o) ? sh[t - o] : 0;
        __syncthreads();
        sh[t] += u;
        __syncthreads();
    }
    if (i < N_NODES) {
        int off = g_bsum[blockIdx.x] + sh[t] - v;   // exclusive
        g_row_ptr[i] = off;
        g_row_fill[i] = off;
    }
    if (i == 0) g_row_ptr[N_NODES] = N_EDGES;
}

// ---------------- fill CSR: interleaved (src, norm-weight) -----------------
__global__ void k_fill(const int* __restrict__ ei, const float* __restrict__ ew) {
    int e = blockIdx.x * blockDim.x + threadIdx.x;
    if (e >= N_EDGES) return;
    int src = ei[e], dst = ei[N_EDGES + e];
    int pos = atomicAdd(&g_row_fill[dst], 1);
    float w = g_dinv[src] * ew[e] * g_dinv[dst];
    g_col[pos] = make_int2(src, __float_as_int(w));
}

// ---------------- precompute W tf32 fragments (all 4 layers) ---------------
__global__ void k_wfrag(const float* __restrict__ W0, const float* __restrict__ W1,
                        const float* __restrict__ W2, const float* __restrict__ W3) {
    int idx = blockIdx.x * 256 + threadIdx.x;     // 4*8*16*32 = 16384
    if (idx >= 4 * 8 * 16 * 32) return;
    int layer = idx >> 12;
    int rem = idx & 4095;
    int s2 = rem >> 9;           // k-step pair (0..7)
    int t  = (rem >> 5) & 15;    // n-tile (0..15)
    int lane = rem & 31;
    int tg = lane & 3, gid = lane >> 2;
    const float* W = (layer == 0) ? W0 : (layer == 1) ? W1 : (layer == 2) ? W2 : W3;
    int n = t * 8 + gid;
    int k0 = s2 * 16;
    float4 v;
    v.x = __uint_as_float(cvt_tf32(W[(k0 + tg) * HID + n]));
    v.y = __uint_as_float(cvt_tf32(W[(k0 + tg + 4) * HID + n]));
    v.z = __uint_as_float(cvt_tf32(W[(k0 + 8 + tg) * HID + n]));
    v.w = __uint_as_float(cvt_tf32(W[(k0 + 12 + tg) * HID + n]));
    g_Wfrag[idx] = v;
}

// ---------------- GEMM via mma.sync tf32: T = act(X) @ W ------------------
#define GTILE 128
#define XS_STRIDE 132
#define GEMM_SMEM (GTILE * XS_STRIDE * 4)

__device__ __forceinline__ void mma_tf32(float* d, uint32_t a0, uint32_t a1,
                                         uint32_t a2, uint32_t a3,
                                         float bx, float by) {
    asm volatile(
        "mma.sync.aligned.m16n8k8.row.col.f32.tf32.tf32.f32 "
        "{%0,%1,%2,%3}, {%4,%5,%6,%7}, {%8,%9}, {%0,%1,%2,%3};"
        : "+f"(d[0]), "+f"(d[1]), "+f"(d[2]), "+f"(d[3])
        : "r"(a0), "r"(a1), "r"(a2), "r"(a3),
          "r"(__float_as_uint(bx)), "r"(__float_as_uint(by)));
}

__global__ void __launch_bounds__(256) k_gemm_mma(const float* __restrict__ X,
                                                  float* __restrict__ T,
                                                  int layer, int relu_in) {
    extern __shared__ uint32_t Xs[];   // [128][132] tf32 bits
    int tid = threadIdx.x;
    int wid = tid >> 5;
    int lane = tid & 31;
    int row0 = blockIdx.x * GTILE;

    // stage X tile (relu + tf32 convert)
    #pragma unroll
    for (int it = 0; it < 16; it++) {
        int i = tid + it * 256;            // row = i>>5, kg = i&31
        int row = i >> 5;
        int kg = i & 31;
        int grow = row0 + row;
        float4 v = make_float4(0.f, 0.f, 0.f, 0.f);
        if (grow < N_NODES) {
            v = *(const float4*)(X + (size_t)grow * HID + kg * 4);
            if (relu_in) {
                v.x = fmaxf(v.x, 0.f); v.y = fmaxf(v.y, 0.f);
                v.z = fmaxf(v.z, 0.f); v.w = fmaxf(v.w, 0.f);
            }
        }
        uint32_t* dst = Xs + row * XS_STRIDE + kg * 4;
        dst[0] = cvt_tf32(v.x); dst[1] = cvt_tf32(v.y);
        dst[2] = cvt_tf32(v.z); dst[3] = cvt_tf32(v.w);
    }
    __syncthreads();

    int tg = lane & 3, gid = lane >> 2;
    float acc[16][4];
    #pragma unroll
    for (int t = 0; t < 16; t++)
        #pragma unroll
        for (int j = 0; j < 4; j++) acc[t][j] = 0.f;

    const uint32_t* arow_lo = Xs + (wid * 16 + gid) * XS_STRIDE;
    const uint32_t* arow_hi = arow_lo + 8 * XS_STRIDE;
    const float4* frag = g_Wfrag + (size_t)layer * 4096 + lane;

    #pragma unroll
    for (int s2 = 0; s2 < 8; s2++) {
        int k0 = s2 * 16;
        uint32_t ae0 = arow_lo[k0 + tg];
        uint32_t ae1 = arow_hi[k0 + tg];
        uint32_t ae2 = arow_lo[k0 + tg + 4];
        uint32_t ae3 = arow_hi[k0 + tg + 4];
        uint32_t ao0 = arow_lo[k0 + 8 + tg];
        uint32_t ao1 = arow_hi[k0 + 8 + tg];
        uint32_t ao2 = arow_lo[k0 + 12 + tg];
        uint32_t ao3 = arow_hi[k0 + 12 + tg];
        const float4* f = frag + s2 * 512;   // [t][lane] stride 32
        #pragma unroll
        for (int t = 0; t < 16; t++) {
            float4 b = f[t * 32];
            mma_tf32(acc[t], ae0, ae1, ae2, ae3, b.x, b.y);
            mma_tf32(acc[t], ao0, ao1, ao2, ao3, b.z, b.w);
        }
    }

    // epilogue: D layout m16n8 -> d0,d1: (gid, tg*2 / tg*2+1); d2,d3: (gid+8, ...)
    int row_lo = row0 + wid * 16 + gid;
    int row_hi = row_lo + 8;
    #pragma unroll
    for (int t = 0; t < 16; t++) {
        int col = t * 8 + tg * 2;
        if (row_lo < N_NODES)
            *(float2*)(T + (size_t)row_lo * HID + col) = make_float2(acc[t][0], acc[t][1]);
        if (row_hi < N_NODES)
            *(float2*)(T + (size_t)row_hi * HID + col) = make_float2(acc[t][2], acc[t][3]);
    }
}

// ---------------- aggregate core: acc = b + T[d]*dinv^2 + sum_e w_e*T[src_e] --
__device__ __forceinline__ float4 aggregate_row(int node, int lane,
                                                const float* __restrict__ b) {
    int beg = __ldg(&g_row_ptr[node]);
    int end = __ldg(&g_row_ptr[node + 1]);
    float di = __ldg(&g_dinv[node]);
    float sw = di * di;   // self-loop weight

    float4 acc = ((const float4*)b)[lane];
    float4 t = ((const float4*)(g_T + (size_t)node * HID))[lane];
    acc.x += t.x * sw; acc.y += t.y * sw; acc.z += t.z * sw; acc.w += t.w * sw;

    int e = beg;
    for (; e + 4 <= end; e += 4) {
        int2 c0 = __ldg(&g_col[e + 0]);
        int2 c1 = __ldg(&g_col[e + 1]);
        int2 c2 = __ldg(&g_col[e + 2]);
        int2 c3 = __ldg(&g_col[e + 3]);
        float4 v0 = ((const float4*)(g_T + (size_t)c0.x * HID))[lane];
        float4 v1 = ((const float4*)(g_T + (size_t)c1.x * HID))[lane];
        float4 v2 = ((const float4*)(g_T + (size_t)c2.x * HID))[lane];
        float4 v3 = ((const float4*)(g_T + (size_t)c3.x * HID))[lane];
        float w0 = __int_as_float(c0.y), w1 = __int_as_float(c1.y);
        float w2 = __int_as_float(c2.y), w3 = __int_as_float(c3.y);
        acc.x += v0.x * w0; acc.y += v0.y * w0; acc.z += v0.z * w0; acc.w += v0.w * w0;
        acc.x += v1.x * w1; acc.y += v1.y * w1; acc.z += v1.z * w1; acc.w += v1.w * w1;
        acc.x += v2.x * w2; acc.y += v2.y * w2; acc.z += v2.z * w2; acc.w += v2.w * w2;
        acc.x += v3.x * w3; acc.y += v3.y * w3; acc.z += v3.z * w3; acc.w += v3.w * w3;
    }
    for (; e < end; e++) {
        int2 c = __ldg(&g_col[e]);
        float w = __int_as_float(c.y);
        float4 v = ((const float4*)(g_T + (size_t)c.x * HID))[lane];
        acc.x += v.x * w; acc.y += v.y * w; acc.z += v.z * w; acc.w += v.w * w;
    }
    return acc;
}

// layers 0-2: write A
__global__ void k_aggregate(const float* __restrict__ b) {
    int node = (blockIdx.x * blockDim.x + threadIdx.x) >> 5;
    int lane = threadIdx.x & 31;
    if (node >= N_NODES) return;
    float4 acc = aggregate_row(node, lane, b);
    ((float4*)(g_A + (size_t)node * HID))[lane] = acc;
}

// layer 3: relu + pool directly (skip A round-trip and k_pool)
__global__ void k_aggregate_pool(const float* __restrict__ b,
                                 const int* __restrict__ batch) {
    int node = (blockIdx.x * blockDim.x + threadIdx.x) >> 5;
    int lane = threadIdx.x & 31;
    if (node >= N_NODES) return;
    float4 acc = aggregate_row(node, lane, b);
    acc.x = fmaxf(acc.x, 0.f); acc.y = fmaxf(acc.y, 0.f);
    acc.z = fmaxf(acc.z, 0.f); acc.w = fmaxf(acc.w, 0.f);
    int g = __ldg(&batch[node]);
    float* d = g_pool + g * HID + lane * 4;
    asm volatile("red.global.add.v4.f32 [%0], {%1,%2,%3,%4};"
                 :: "l"(d), "f"(acc.x), "f"(acc.y), "f"(acc.z), "f"(acc.w) : "memory");
    if (lane == 0) atomicAdd(&g_cnt[g], 1.0f);
}

// ---------------- pooling buffers ----------------
__global__ void k_zero_pool() {
    int i = blockIdx.x * blockDim.x + threadIdx.x;
    if (i < N_GRAPHS * HID) g_pool[i] = 0.f;
    if (i < N_GRAPHS) g_cnt[i] = 0.f;
}

// ---------------- head ----------------
__global__ void k_final(const float* __restrict__ Wc, const float* __restrict__ bc,
                        float* __restrict__ out) {
    int g = blockIdx.x;
    int c = threadIdx.x;     // 128
    float cn = fmaxf(g_cnt[g], 1.0f);
    float v = g_pool[g * HID + c] / cn * Wc[c];
    #pragma unroll
    for (int o = 16; o > 0; o >>= 1) v += __shfl_down_sync(0xffffffffu, v, o);
    __shared__ float ss[4];
    if ((c & 31) == 0) ss[c >> 5] = v;
    __syncthreads();
    if (c == 0) {
        float s = ss[0] + ss[1] + ss[2] + ss[3] + bc[0];
        out[g] = 1.0f / (1.0f + expf(-s));
    }
}

// ---------------- launch ----------------
extern "C" void kernel_launch(void* const* d_in, const int* in_sizes, int n_in,
                              void* d_out, int out_size) {
    const float* x   = (const float*)d_in[0];
    const int*   ei  = (const int*)d_in[1];
    const float* ew  = (const float*)d_in[2];
    const int*   bat = (const int*)d_in[3];
    const float* W[4]  = { (const float*)d_in[4], (const float*)d_in[6],
                           (const float*)d_in[8], (const float*)d_in[10] };
    const float* B[4]  = { (const float*)d_in[5], (const float*)d_in[7],
                           (const float*)d_in[9], (const float*)d_in[11] };
    const float* Wc  = (const float*)d_in[12];
    const float* bc  = (const float*)d_in[13];
    float* out = (float*)d_out;

    cudaFuncSetAttribute(k_gemm_mma, cudaFuncAttributeMaxDynamicSharedMemorySize,
                         GEMM_SMEM);

    float* T_ptr; cudaGetSymbolAddress((void**)&T_ptr, g_T);
    float* A_ptr; cudaGetSymbolAddress((void**)&A_ptr, g_A);

    // ---- preprocessing: degrees + CSR build + W fragments + pool zero ----
    k_init_deg<<<(N_NODES + 255) / 256, 256>>>();
    k_accum_deg<<<(N_EDGES + 255) / 256, 256>>>(ei, ew);
    k_dinv<<<(N_NODES + 255) / 256, 256>>>();
    k_scan1<<<SCAN_BLK, 256>>>();
    k_scan2<<<1, 512>>>();
    k_scan3<<<SCAN_BLK, 256>>>();
    k_fill<<<(N_EDGES + 255) / 256, 256>>>(ei, ew);
    k_wfrag<<<64, 256>>>(W[0], W[1], W[2], W[3]);
    k_zero_pool<<<(N_GRAPHS * HID + 255) / 256, 256>>>();

    const int gemm_grid = (N_NODES + GTILE - 1) / GTILE;     // 782
    const int aggr_grid = (N_NODES * 32 + 255) / 256;        // warp per node

    // ---- 4 GCN layers (last one fuses relu+pool) ----
    for (int l = 0; l < 4; l++) {
        const float* in = (l == 0) ? x : A_ptr;
        int relu_in = (l == 0) ? 0 : 1;
        k_gemm_mma<<<gemm_grid, 256, GEMM_SMEM>>>(in, T_ptr, l, relu_in);
        if (l < 3)
            k_aggregate<<<aggr_grid, 256>>>(B[l]);
        else
            k_aggregate_pool<<<aggr_grid, 256>>>(B[l], bat);
    }

    // ---- head ----
    k_final<<<N_GRAPHS, HID>>>(Wc, bc, out);
}

// round 10
// speedup vs baseline: 1.5555x; 1.2237x over previous
#include <cuda_runtime.h>
#include <cuda_bf16.h>
#include <cstdint>

#define N_NODES 100000
#define N_EDGES 3200000
#define HID 128
#define N_GRAPHS 512

// ---------------- scratch (device globals; no allocation allowed) ----------
__device__ uint32_t g_Th[(size_t)N_NODES * 64];  // T as packed bf16x2 (128 cols)
__device__ float g_A[(size_t)N_NODES * HID];     // aggregated output (fp32)
__device__ float g_deg[N_NODES];
__device__ float g_dinv[N_NODES];
__device__ float g_pool[N_GRAPHS * HID];
__device__ float g_cnt[N_GRAPHS];
// CSR (by destination) — interleaved (src, weight_bits)
__device__ int   g_row_ptr[N_NODES + 1];
__device__ int   g_row_fill[N_NODES];
__device__ int2  g_col[N_EDGES];
__device__ int   g_hist[N_NODES];

#define SCAN_BLK 391            // ceil(100000/256)
__device__ int   g_bsum[512];   // block sums (padded)

// tf32 B-fragments for all 4 layers:
// layout [layer][s2(8)][t(16)][lane(32)] -> float4 = (b0_even, b1_even, b0_odd, b1_odd)
__device__ float4 g_Wfrag[4 * 8 * 16 * 32];

__device__ __forceinline__ uint32_t cvt_tf32(float f) {
    uint32_t u;
    asm("cvt.rna.tf32.f32 %0, %1;" : "=r"(u) : "f"(f));
    return u;
}

// ---------------- degree / norm ----------------
__global__ void k_init_deg() {
    int i = blockIdx.x * blockDim.x + threadIdx.x;
    if (i < N_NODES) { g_deg[i] = 1.0f; g_hist[i] = 0; }   // self-loop weight
}

__global__ void k_accum_deg(const int* __restrict__ ei, const float* __restrict__ ew) {
    int e = blockIdx.x * blockDim.x + threadIdx.x;
    if (e >= N_EDGES) return;
    int dst = ei[N_EDGES + e];
    atomicAdd(&g_deg[dst], ew[e]);
    atomicAdd(&g_hist[dst], 1);
}

__global__ void k_dinv() {
    int i = blockIdx.x * blockDim.x + threadIdx.x;
    if (i < N_NODES) g_dinv[i] = rsqrtf(g_deg[i]);   // deg >= 1 always
}

// ---------------- 3-phase parallel exclusive scan over g_hist --------------
__global__ void k_scan1() {
    __shared__ int sh[256];
    int i = blockIdx.x * 256 + threadIdx.x;
    int v = (i < N_NODES) ? g_hist[i] : 0;
    sh[threadIdx.x] = v;
    __syncthreads();
    #pragma unroll
    for (int o = 128; o > 0; o >>= 1) {
        if (threadIdx.x < o) sh[threadIdx.x] += sh[threadIdx.x + o];
        __syncthreads();
    }
    if (threadIdx.x == 0) g_bsum[blockIdx.x] = sh[0];
}

__global__ void k_scan2() {
    __shared__ int sh[512];
    int t = threadIdx.x;
    sh[t] = (t < SCAN_BLK) ? g_bsum[t] : 0;
    __syncthreads();
    #pragma unroll
    for (int o = 1; o < 512; o <<= 1) {
        int v = (t >= o) ? sh[t - o] : 0;
        __syncthreads();
        sh[t] += v;
        __syncthreads();
    }
    if (t < SCAN_BLK) g_bsum[t] = (t == 0) ? 0 : sh[t - 1];   // exclusive
}

__global__ void k_scan3() {
    __shared__ int sh[256];
    int t = threadIdx.x;
    int i = blockIdx.x * 256 + t;
    int v = (i < N_NODES) ? g_hist[i] : 0;
    sh[t] = v;
    __syncthreads();
    #pragma unroll
    for (int o = 1; o < 256; o <<= 1) {
        int u = (t >= o) ? sh[t - o] : 0;
        __syncthreads();
        sh[t] += u;
        __syncthreads();
    }
    if (i < N_NODES) {
        int off = g_bsum[blockIdx.x] + sh[t] - v;   // exclusive
        g_row_ptr[i] = off;
        g_row_fill[i] = off;
    }
    if (i == 0) g_row_ptr[N_NODES] = N_EDGES;
}

// ---------------- fill CSR: interleaved (src, norm-weight) -----------------
__global__ void k_fill(const int* __restrict__ ei, const float* __restrict__ ew) {
    int e = blockIdx.x * blockDim.x + threadIdx.x;
    if (e >= N_EDGES) return;
    int src = ei[e], dst = ei[N_EDGES + e];
    int pos = atomicAdd(&g_row_fill[dst], 1);
    float w = g_dinv[src] * ew[e] * g_dinv[dst];
    g_col[pos] = make_int2(src, __float_as_int(w));
}

// ---------------- precompute W tf32 fragments (all 4 layers) ---------------
__global__ void k_wfrag(const float* __restrict__ W0, const float* __restrict__ W1,
                        const float* __restrict__ W2, const float* __restrict__ W3) {
    int idx = blockIdx.x * 256 + threadIdx.x;     // 4*8*16*32 = 16384
    if (idx >= 4 * 8 * 16 * 32) return;
    int layer = idx >> 12;
    int rem = idx & 4095;
    int s2 = rem >> 9;           // k-step pair (0..7)
    int t  = (rem >> 5) & 15;    // n-tile (0..15)
    int lane = rem & 31;
    int tg = lane & 3, gid = lane >> 2;
    const float* W = (layer == 0) ? W0 : (layer == 1) ? W1 : (layer == 2) ? W2 : W3;
    int n = t * 8 + gid;
    int k0 = s2 * 16;
    float4 v;
    v.x = __uint_as_float(cvt_tf32(W[(k0 + tg) * HID + n]));
    v.y = __uint_as_float(cvt_tf32(W[(k0 + tg + 4) * HID + n]));
    v.z = __uint_as_float(cvt_tf32(W[(k0 + 8 + tg) * HID + n]));
    v.w = __uint_as_float(cvt_tf32(W[(k0 + 12 + tg) * HID + n]));
    g_Wfrag[idx] = v;
}

// ---------------- GEMM via mma.sync tf32: Th = bf16(act(X) @ W) ------------
#define GTILE 128
#define XS_STRIDE 132
#define ST_STRIDE 68   // bf16 stage stride (words); conflict-free, 16B-aligned
#define GEMM_SMEM (GTILE * XS_STRIDE * 4)

__device__ __forceinline__ void mma_tf32(float* d, uint32_t a0, uint32_t a1,
                                         uint32_t a2, uint32_t a3,
                                         float bx, float by) {
    asm volatile(
        "mma.sync.aligned.m16n8k8.row.col.f32.tf32.tf32.f32 "
        "{%0,%1,%2,%3}, {%4,%5,%6,%7}, {%8,%9}, {%0,%1,%2,%3};"
        : "+f"(d[0]), "+f"(d[1]), "+f"(d[2]), "+f"(d[3])
        : "r"(a0), "r"(a1), "r"(a2), "r"(a3),
          "r"(__float_as_uint(bx)), "r"(__float_as_uint(by)));
}

__device__ __forceinline__ uint32_t pack_bf16x2(float a, float b) {
    __nv_bfloat162 h = __float22bfloat162_rn(make_float2(a, b));
    return *(uint32_t*)&h;
}

__global__ void __launch_bounds__(256) k_gemm_mma(const float* __restrict__ X,
                                                  int layer, int relu_in) {
    extern __shared__ uint32_t Xs[];   // [128][132] tf32 bits; reused as bf16 stage
    int tid = threadIdx.x;
    int wid = tid >> 5;
    int lane = tid & 31;
    int row0 = blockIdx.x * GTILE;

    // stage X tile (relu + tf32 convert)
    #pragma unroll
    for (int it = 0; it < 16; it++) {
        int i = tid + it * 256;            // row = i>>5, kg = i&31
        int row = i >> 5;
        int kg = i & 31;
        int grow = row0 + row;
        float4 v = make_float4(0.f, 0.f, 0.f, 0.f);
        if (grow < N_NODES) {
            v = *(const float4*)(X + (size_t)grow * HID + kg * 4);
            if (relu_in) {
                v.x = fmaxf(v.x, 0.f); v.y = fmaxf(v.y, 0.f);
                v.z = fmaxf(v.z, 0.f); v.w = fmaxf(v.w, 0.f);
            }
        }
        uint32_t* dst = Xs + row * XS_STRIDE + kg * 4;
        dst[0] = cvt_tf32(v.x); dst[1] = cvt_tf32(v.y);
        dst[2] = cvt_tf32(v.z); dst[3] = cvt_tf32(v.w);
    }
    __syncthreads();

    int tg = lane & 3, gid = lane >> 2;
    float acc[16][4];
    #pragma unroll
    for (int t = 0; t < 16; t++)
        #pragma unroll
        for (int j = 0; j < 4; j++) acc[t][j] = 0.f;

    const uint32_t* arow_lo = Xs + (wid * 16 + gid) * XS_STRIDE;
    const uint32_t* arow_hi = arow_lo + 8 * XS_STRIDE;
    const float4* frag = g_Wfrag + (size_t)layer * 4096 + lane;

    #pragma unroll
    for (int s2 = 0; s2 < 8; s2++) {
        int k0 = s2 * 16;
        uint32_t ae0 = arow_lo[k0 + tg];
        uint32_t ae1 = arow_hi[k0 + tg];
        uint32_t ae2 = arow_lo[k0 + tg + 4];
        uint32_t ae3 = arow_hi[k0 + tg + 4];
        uint32_t ao0 = arow_lo[k0 + 8 + tg];
        uint32_t ao1 = arow_hi[k0 + 8 + tg];
        uint32_t ao2 = arow_lo[k0 + 12 + tg];
        uint32_t ao3 = arow_hi[k0 + 12 + tg];
        const float4* f = frag + s2 * 512;   // [t][lane] stride 32
        #pragma unroll
        for (int t = 0; t < 16; t++) {
            float4 b = f[t * 32];
            mma_tf32(acc[t], ae0, ae1, ae2, ae3, b.x, b.y);
            mma_tf32(acc[t], ao0, ao1, ao2, ao3, b.z, b.w);
        }
    }

    // epilogue: stage bf16x2 rows in smem (conflict-free), then coalesced STG
    __syncthreads();   // all warps done reading Xs
    uint32_t* St = Xs; // reuse: [128][ST_STRIDE]
    int lrow_lo = wid * 16 + gid;
    #pragma unroll
    for (int t = 0; t < 16; t++) {
        int widx = t * 4 + tg;
        St[lrow_lo * ST_STRIDE + widx]       = pack_bf16x2(acc[t][0], acc[t][1]);
        St[(lrow_lo + 8) * ST_STRIDE + widx] = pack_bf16x2(acc[t][2], acc[t][3]);
    }
    __syncthreads();
    // copy 128 rows x 64 words = 2048 uint4 -> fully coalesced in g_Th
    #pragma unroll
    for (int it = 0; it < 8; it++) {
        int j = tid + it * 256;        // j in [0,2048): row = j>>4, w4 = j&15
        int row = j >> 4;
        int w4 = j & 15;
        int grow = row0 + row;
        if (grow < N_NODES) {
            uint4 v = *(const uint4*)&St[row * ST_STRIDE + w4 * 4];
            *(uint4*)(g_Th + (size_t)grow * 64 + w4 * 4) = v;
        }
    }
}

// ---------------- aggregate core: acc = b + Th[d]*dinv^2 + sum w_e*Th[src] ----
__device__ __forceinline__ void bf2_fma(float4& acc, uint2 p, float w) {
    float2 lo = __bfloat1622float2(*(__nv_bfloat162*)&p.x);
    float2 hi = __bfloat1622float2(*(__nv_bfloat162*)&p.y);
    acc.x += lo.x * w; acc.y += lo.y * w; acc.z += hi.x * w; acc.w += hi.y * w;
}

__device__ __forceinline__ float4 aggregate_row(int node, int lane,
                                                const float* __restrict__ b) {
    int beg = __ldg(&g_row_ptr[node]);
    int end = __ldg(&g_row_ptr[node + 1]);
    float di = __ldg(&g_dinv[node]);
    float sw = di * di;   // self-loop weight

    float4 acc = ((const float4*)b)[lane];
    uint2 ts = *(const uint2*)(g_Th + (size_t)node * 64 + lane * 2);
    bf2_fma(acc, ts, sw);

    int e = beg;
    for (; e + 4 <= end; e += 4) {
        int2 c0 = __ldg(&g_col[e + 0]);
        int2 c1 = __ldg(&g_col[e + 1]);
        int2 c2 = __ldg(&g_col[e + 2]);
        int2 c3 = __ldg(&g_col[e + 3]);
        uint2 v0 = *(const uint2*)(g_Th + (size_t)c0.x * 64 + lane * 2);
        uint2 v1 = *(const uint2*)(g_Th + (size_t)c1.x * 64 + lane * 2);
        uint2 v2 = *(const uint2*)(g_Th + (size_t)c2.x * 64 + lane * 2);
        uint2 v3 = *(const uint2*)(g_Th + (size_t)c3.x * 64 + lane * 2);
        bf2_fma(acc, v0, __int_as_float(c0.y));
        bf2_fma(acc, v1, __int_as_float(c1.y));
        bf2_fma(acc, v2, __int_as_float(c2.y));
        bf2_fma(acc, v3, __int_as_float(c3.y));
    }
    for (; e < end; e++) {
        int2 c = __ldg(&g_col[e]);
        uint2 v = *(const uint2*)(g_Th + (size_t)c.x * 64 + lane * 2);
        bf2_fma(acc, v, __int_as_float(c.y));
    }
    return acc;
}

// layers 0-2: write fp32 A
__global__ void k_aggregate(const float* __restrict__ b) {
    int node = (blockIdx.x * blockDim.x + threadIdx.x) >> 5;
    int lane = threadIdx.x & 31;
    if (node >= N_NODES) return;
    float4 acc = aggregate_row(node, lane, b);
    ((float4*)(g_A + (size_t)node * HID))[lane] = acc;
}

// layer 3: relu + pool directly (skip A round-trip)
__global__ void k_aggregate_pool(const float* __restrict__ b,
                                 const int* __restrict__ batch) {
    int node = (blockIdx.x * blockDim.x + threadIdx.x) >> 5;
    int lane = threadIdx.x & 31;
    if (node >= N_NODES) return;
    float4 acc = aggregate_row(node, lane, b);
    acc.x = fmaxf(acc.x, 0.f); acc.y = fmaxf(acc.y, 0.f);
    acc.z = fmaxf(acc.z, 0.f); acc.w = fmaxf(acc.w, 0.f);
    int g = __ldg(&batch[node]);
    float* d = g_pool + g * HID + lane * 4;
    asm volatile("red.global.add.v4.f32 [%0], {%1,%2,%3,%4};"
                 :: "l"(d), "f"(acc.x), "f"(acc.y), "f"(acc.z), "f"(acc.w) : "memory");
    if (lane == 0) atomicAdd(&g_cnt[g], 1.0f);
}

// ---------------- pooling buffers ----------------
__global__ void k_zero_pool() {
    int i = blockIdx.x * blockDim.x + threadIdx.x;
    if (i < N_GRAPHS * HID) g_pool[i] = 0.f;
    if (i < N_GRAPHS) g_cnt[i] = 0.f;
}

// ---------------- head ----------------
__global__ void k_final(const float* __restrict__ Wc, const float* __restrict__ bc,
                        float* __restrict__ out) {
    int g = blockIdx.x;
    int c = threadIdx.x;     // 128
    float cn = fmaxf(g_cnt[g], 1.0f);
    float v = g_pool[g * HID + c] / cn * Wc[c];
    #pragma unroll
    for (int o = 16; o > 0; o >>= 1) v += __shfl_down_sync(0xffffffffu, v, o);
    __shared__ float ss[4];
    if ((c & 31) == 0) ss[c >> 5] = v;
    __syncthreads();
    if (c == 0) {
        float s = ss[0] + ss[1] + ss[2] + ss[3] + bc[0];
        out[g] = 1.0f / (1.0f + expf(-s));
    }
}

// ---------------- launch ----------------
extern "C" void kernel_launch(void* const* d_in, const int* in_sizes, int n_in,
                              void* d_out, int out_size) {
    const float* x   = (const float*)d_in[0];
    const int*   ei  = (const int*)d_in[1];
    const float* ew  = (const float*)d_in[2];
    const int*   bat = (const int*)d_in[3];
    const float* W[4]  = { (const float*)d_in[4], (const float*)d_in[6],
                           (const float*)d_in[8], (const float*)d_in[10] };
    const float* B[4]  = { (const float*)d_in[5], (const float*)d_in[7],
                           (const float*)d_in[9], (const float*)d_in[11] };
    const float* Wc  = (const float*)d_in[12];
    const float* bc  = (const float*)d_in[13];
    float* out = (float*)d_out;

    cudaFuncSetAttribute(k_gemm_mma, cudaFuncAttributeMaxDynamicSharedMemorySize,
                         GEMM_SMEM);

    float* A_ptr; cudaGetSymbolAddress((void**)&A_ptr, g_A);

    // ---- preprocessing: degrees + CSR build + W fragments + pool zero ----
    k_init_deg<<<(N_NODES + 255) / 256, 256>>>();
    k_accum_deg<<<(N_EDGES + 255) / 256, 256>>>(ei, ew);
    k_dinv<<<(N_NODES + 255) / 256, 256>>>();
    k_scan1<<<SCAN_BLK, 256>>>();
    k_scan2<<<1, 512>>>();
    k_scan3<<<SCAN_BLK, 256>>>();
    k_fill<<<(N_EDGES + 255) / 256, 256>>>(ei, ew);
    k_wfrag<<<64, 256>>>(W[0], W[1], W[2], W[3]);
    k_zero_pool<<<(N_GRAPHS * HID + 255) / 256, 256>>>();

    const int gemm_grid = (N_NODES + GTILE - 1) / GTILE;     // 782
    const int aggr_grid = (N_NODES * 32 + 255) / 256;        // warp per node

    // ---- 4 GCN layers (last one fuses relu+pool) ----
    for (int l = 0; l < 4; l++) {
        const float* in = (l == 0) ? x : A_ptr;
        int relu_in = (l == 0) ? 0 : 1;
        k_gemm_mma<<<gemm_grid, 256, GEMM_SMEM>>>(in, l, relu_in);
        if (l < 3)
            k_aggregate<<<aggr_grid, 256>>>(B[l]);
        else
            k_aggregate_pool<<<aggr_grid, 256>>>(B[l], bat);
    }

    // ---- head ----
    k_final<<<N_GRAPHS, HID>>>(Wc, bc, out);
}